// round 5
// baseline (speedup 1.0000x reference)
#include <cuda_runtime.h>
#include <cuda_bf16.h>

#define H 512
#define W 512
#define OW 510                  // windows per dim
#define PLANE (H * W)
#define WIN_PER_WARP 62         // 31 lanes x 2 windows (even/odd)
#define COLGROUPS 9             // ceil(510 / 62)
#define NTASKS (OW * COLGROUPS) // 510 * 9 = 4590 warp-tasks
#define WARPS_PER_BLOCK 4
#define NBLOCKS ((NTASKS + WARPS_PER_BLOCK - 1) / WARPS_PER_BLOCK)   // 1148

__device__ double       g_accum;   // zero-init; restored to 0 each call
__device__ unsigned int g_cnt;     // zero-init; restored to 0 each call

static __device__ __forceinline__ float2 operator+(float2 a, float2 b){ return make_float2(a.x+b.x, a.y+b.y); }
static __device__ __forceinline__ float2 operator-(float2 a, float2 b){ return make_float2(a.x-b.x, a.y-b.y); }
static __device__ __forceinline__ float2 operator*(float2 a, float2 b){ return make_float2(a.x*b.x, a.y*b.y); }
static __device__ __forceinline__ float2 operator*(float s,  float2 b){ return make_float2(s*b.x,  s*b.y ); }
static __device__ __forceinline__ float2 f2rcp(float2 a){ return make_float2(1.0f/a.x, 1.0f/a.y); }

__global__ __launch_bounds__(WARPS_PER_BLOCK * 32)
void ml_fused_kernel(const float* __restrict__ T, const float* __restrict__ V,
                     float* __restrict__ out)
{
    const int warp_id  = threadIdx.x >> 5;
    const int lane     = threadIdx.x & 31;
    const int warp_gid = blockIdx.x * WARPS_PER_BLOCK + warp_id;

    float contrib = 0.0f;

    if (warp_gid < NTASKS) {
        const int r    = warp_gid / COLGROUPS;      // window row 0..509
        const int g    = warp_gid % COLGROUPS;      // column group 0..8
        const int x0   = g * WIN_PER_WARP + 2*lane; // even pixel column this lane owns

        // ---- per-column stats for columns x0 (.x) and x0+1 (.y), 22 float2 accs
        float2 sT0={0,0}, sT1={0,0}, sT2={0,0};
        float2 s00={0,0}, s01={0,0}, s02={0,0}, s11={0,0}, s12={0,0}, s22={0,0};
        float2 sV0={0,0}, sV1={0,0}, sV2={0,0};
        float2 sq ={0,0};
        float2 m00={0,0}, m01={0,0}, m02={0,0};
        float2 m10={0,0}, m11={0,0}, m12={0,0};
        float2 m20={0,0}, m21={0,0}, m22={0,0};

        if (x0 <= 510) {   // float2 covers cols x0, x0+1 (x0 even => x0+1 <= 511)
            #pragma unroll
            for (int dr = 0; dr < 3; dr++) {
                const int base = (r + dr) * W + x0;
                const float2 t0 = *reinterpret_cast<const float2*>(T + 0*PLANE + base);
                const float2 t1 = *reinterpret_cast<const float2*>(T + 1*PLANE + base);
                const float2 t2 = *reinterpret_cast<const float2*>(T + 2*PLANE + base);
                const float2 v0 = *reinterpret_cast<const float2*>(V + 0*PLANE + base);
                const float2 v1 = *reinterpret_cast<const float2*>(V + 1*PLANE + base);
                const float2 v2 = *reinterpret_cast<const float2*>(V + 2*PLANE + base);

                sT0 = sT0 + t0;  sT1 = sT1 + t1;  sT2 = sT2 + t2;
                s00 = s00 + t0*t0;  s01 = s01 + t0*t1;  s02 = s02 + t0*t2;
                s11 = s11 + t1*t1;  s12 = s12 + t1*t2;  s22 = s22 + t2*t2;

                sV0 = sV0 + v0;  sV1 = sV1 + v1;  sV2 = sV2 + v2;
                sq  = sq + v0*v0 + v1*v1 + v2*v2;

                m00 = m00 + t0*v0;  m01 = m01 + t0*v1;  m02 = m02 + t0*v2;
                m10 = m10 + t1*v0;  m11 = m11 + t1*v1;  m12 = m12 + t1*v2;
                m20 = m20 + t2*v0;  m21 = m21 + t2*v1;  m22 = m22 + t2*v2;
            }
        }

        // ---- in-place transform: colseg stats -> window stats
        // even window (col x0)  = S.x + S.y + Sn.x    -> stored in .x
        // odd  window (col x0+1)= S.y + Sn.x + Sn.y   -> stored in .y
        #define WTRANS(S) { \
            const float snx = __shfl_down_sync(0xffffffffu, S.x, 1); \
            const float sny = __shfl_down_sync(0xffffffffu, S.y, 1); \
            const float we  = S.x + S.y + snx; \
            const float wo  = S.y + snx + sny; \
            S.x = we; S.y = wo; }
        WTRANS(sT0) WTRANS(sT1) WTRANS(sT2)
        WTRANS(s00) WTRANS(s01) WTRANS(s02) WTRANS(s11) WTRANS(s12) WTRANS(s22)
        WTRANS(sV0) WTRANS(sV1) WTRANS(sV2)
        WTRANS(sq)
        WTRANS(m00) WTRANS(m01) WTRANS(m02)
        WTRANS(m10) WTRANS(m11) WTRANS(m12)
        WTRANS(m20) WTRANS(m21) WTRANS(m22)
        #undef WTRANS

        // windows valid: lane < 31 supplies both, and x0 <= 508 (then x0+1 <= 509)
        if (lane < 31 && x0 <= 508) {
            const float inv9 = 1.0f / 9.0f;
            const float eps9 = 1e-7f * inv9;
            const float2 e9  = make_float2(eps9, eps9);

            const float2 mu0 = inv9 * sT0, mu1 = inv9 * sT1, mu2 = inv9 * sT2;

            const float2 a00 = inv9*s00 - mu0*mu0 + e9;
            const float2 a01 = inv9*s01 - mu0*mu1;
            const float2 a02 = inv9*s02 - mu0*mu2;
            const float2 a11 = inv9*s11 - mu1*mu1 + e9;
            const float2 a12 = inv9*s12 - mu1*mu2;
            const float2 a22 = inv9*s22 - mu2*mu2 + e9;

            const float2 c00 = a11*a22 - a12*a12;
            const float2 c01 = a02*a12 - a01*a22;
            const float2 c02 = a01*a12 - a02*a11;
            const float2 c11 = a00*a22 - a02*a02;
            const float2 c12 = a01*a02 - a00*a12;
            const float2 c22 = a00*a11 - a01*a01;
            const float2 det = a00*c00 + a01*c01 + a02*c02;
            const float2 rdet = f2rcp(det);
            const float2 i00 = c00*rdet, i01 = c01*rdet, i02 = c02*rdet;
            const float2 i11 = c11*rdet, i12 = c12*rdet, i22 = c22*rdet;

            float2 acc = sq;  // sum_c V_c^2 over window
            float2 pen = sV0*sV0 + sV1*sV1 + sV2*sV2;

            // channel 0
            {
                const float2 u0 = m00 - mu0*sV0;
                const float2 u1 = m10 - mu1*sV0;
                const float2 u2 = m20 - mu2*sV0;
                pen = pen + i00*u0*u0 + i11*u1*u1 + i22*u2*u2
                          + 2.f*(i01*u0*u1 + i02*u0*u2 + i12*u1*u2);
            }
            // channel 1
            {
                const float2 u0 = m01 - mu0*sV1;
                const float2 u1 = m11 - mu1*sV1;
                const float2 u2 = m21 - mu2*sV1;
                pen = pen + i00*u0*u0 + i11*u1*u1 + i22*u2*u2
                          + 2.f*(i01*u0*u1 + i02*u0*u2 + i12*u1*u2);
            }
            // channel 2
            {
                const float2 u0 = m02 - mu0*sV2;
                const float2 u1 = m12 - mu1*sV2;
                const float2 u2 = m22 - mu2*sV2;
                pen = pen + i00*u0*u0 + i11*u1*u1 + i22*u2*u2
                          + 2.f*(i01*u0*u1 + i02*u0*u2 + i12*u1*u2);
            }

            const float2 c2 = acc - inv9 * pen;
            contrib = c2.x + c2.y;
        }
    }

    // warp reduction
    #pragma unroll
    for (int off = 16; off > 0; off >>= 1)
        contrib += __shfl_xor_sync(0xffffffffu, contrib, off);

    __shared__ float wsum[WARPS_PER_BLOCK];
    __shared__ bool  is_last;
    if (lane == 0) wsum[warp_id] = contrib;
    __syncthreads();

    if (threadIdx.x == 0) {
        float s = 0.f;
        #pragma unroll
        for (int i = 0; i < WARPS_PER_BLOCK; i++) s += wsum[i];
        atomicAdd(&g_accum, (double)s);
        __threadfence();
        unsigned int prev = atomicAdd(&g_cnt, 1u);
        is_last = (prev == NBLOCKS - 1);
    }
    __syncthreads();

    if (is_last && threadIdx.x == 0) {
        __threadfence();
        out[0] = (float)g_accum;
        g_accum = 0.0;
        g_cnt   = 0;
    }
}

extern "C" void kernel_launch(void* const* d_in, const int* in_sizes, int n_in,
                              void* d_out, int out_size)
{
    const float* target = (const float*)d_in[0];
    const float* style  = (const float*)d_in[1];
    float* out = (float*)d_out;

    ml_fused_kernel<<<NBLOCKS, WARPS_PER_BLOCK * 32>>>(target, style, out);
}

// round 6
// speedup vs baseline: 1.0269x; 1.0269x over previous
#include <cuda_runtime.h>
#include <cuda_bf16.h>

#define H 512
#define W 512
#define OW 510
#define PLANE (H * W)
#define RBLK 3                     // window rows per warp-task
#define PROWS (RBLK + 2)           // pixel rows streamed per task
#define WIN_PER_WARP 30            // 32 lanes -> 30 window cols
#define COLGROUPS 17               // 17 * 30 = 510 exactly
#define ROWGROUPS (OW / RBLK)      // 170 exactly
#define NTASKS (ROWGROUPS * COLGROUPS)   // 2890
#define WARPS_PER_BLOCK 5
#define NBLOCKS (NTASKS / WARPS_PER_BLOCK)   // 578 exactly

__device__ double       g_accum;   // zero-init; restored to 0 each call
__device__ unsigned int g_cnt;     // zero-init; restored to 0 each call

__global__ __launch_bounds__(WARPS_PER_BLOCK * 32)
void ml_fused_kernel(const float* __restrict__ T, const float* __restrict__ V,
                     float* __restrict__ out)
{
    const int warp_id  = threadIdx.x >> 5;
    const int lane     = threadIdx.x & 31;
    const int warp_gid = blockIdx.x * WARPS_PER_BLOCK + warp_id;

    const int rg = warp_gid / COLGROUPS;          // row group 0..169
    const int cg = warp_gid % COLGROUPS;          // col group 0..16
    const int r0 = rg * RBLK;                     // first window row of task
    const int x  = cg * WIN_PER_WARP + lane;      // pixel column 0..511 (always valid)

    float contrib = 0.0f;

    // ring of per-pixel-row stats (22 each), fully unrolled -> registers
    float ring[3][22];

    const float inv9 = 1.0f / 9.0f;
    const float eps9 = 1e-7f * inv9;

    #pragma unroll
    for (int j = 0; j < PROWS; j++) {
        const int base = (r0 + j) * W + x;
        const float t0 = T[0 * PLANE + base];
        const float t1 = T[1 * PLANE + base];
        const float t2 = T[2 * PLANE + base];
        const float v0 = V[0 * PLANE + base];
        const float v1 = V[1 * PLANE + base];
        const float v2 = V[2 * PLANE + base];

        float* rs = ring[j % 3];
        rs[0]  = t0;      rs[1]  = t1;      rs[2]  = t2;
        rs[3]  = v0;      rs[4]  = v1;      rs[5]  = v2;
        rs[6]  = t0 * t0; rs[7]  = t0 * t1; rs[8]  = t0 * t2;
        rs[9]  = t1 * t1; rs[10] = t1 * t2; rs[11] = t2 * t2;
        rs[12] = v0 * v0 + v1 * v1 + v2 * v2;
        rs[13] = t0 * v0; rs[14] = t0 * v1; rs[15] = t0 * v2;
        rs[16] = t1 * v0; rs[17] = t1 * v1; rs[18] = t1 * v2;
        rs[19] = t2 * v0; rs[20] = t2 * v1; rs[21] = t2 * v2;

        if (j >= 2) {
            // column-segment stats = sum of the 3 resident rows
            float cs[22];
            #pragma unroll
            for (int k = 0; k < 22; k++)
                cs[k] = ring[0][k] + ring[1][k] + ring[2][k];

            // horizontal window sum across 3 columns (lane, lane+1, lane+2)
            #pragma unroll
            for (int k = 0; k < 22; k++) {
                const float a = __shfl_down_sync(0xffffffffu, cs[k], 1);
                const float b = __shfl_down_sync(0xffffffffu, cs[k], 2);
                cs[k] += a + b;
            }

            // per-window math (valid for lane < 30)
            const float mu0 = cs[0] * inv9, mu1 = cs[1] * inv9, mu2 = cs[2] * inv9;
            const float sV0 = cs[3], sV1 = cs[4], sV2 = cs[5];

            const float a00 = cs[6]  * inv9 - mu0 * mu0 + eps9;
            const float a01 = cs[7]  * inv9 - mu0 * mu1;
            const float a02 = cs[8]  * inv9 - mu0 * mu2;
            const float a11 = cs[9]  * inv9 - mu1 * mu1 + eps9;
            const float a12 = cs[10] * inv9 - mu1 * mu2;
            const float a22 = cs[11] * inv9 - mu2 * mu2 + eps9;

            const float c00 = a11 * a22 - a12 * a12;
            const float c01 = a02 * a12 - a01 * a22;
            const float c02 = a01 * a12 - a02 * a11;
            const float c11 = a00 * a22 - a02 * a02;
            const float c12 = a01 * a02 - a00 * a12;
            const float c22 = a00 * a11 - a01 * a01;
            const float det = a00 * c00 + a01 * c01 + a02 * c02;
            const float rdet = 1.0f / det;
            const float i00 = c00 * rdet, i01 = c01 * rdet, i02 = c02 * rdet;
            const float i11 = c11 * rdet, i12 = c12 * rdet, i22 = c22 * rdet;

            float pen = sV0 * sV0 + sV1 * sV1 + sV2 * sV2;

            // channel 0
            {
                const float u0 = cs[13] - mu0 * sV0;
                const float u1 = cs[16] - mu1 * sV0;
                const float u2 = cs[19] - mu2 * sV0;
                pen += i00 * u0 * u0 + i11 * u1 * u1 + i22 * u2 * u2
                     + 2.f * (i01 * u0 * u1 + i02 * u0 * u2 + i12 * u1 * u2);
            }
            // channel 1
            {
                const float u0 = cs[14] - mu0 * sV1;
                const float u1 = cs[17] - mu1 * sV1;
                const float u2 = cs[20] - mu2 * sV1;
                pen += i00 * u0 * u0 + i11 * u1 * u1 + i22 * u2 * u2
                     + 2.f * (i01 * u0 * u1 + i02 * u0 * u2 + i12 * u1 * u2);
            }
            // channel 2
            {
                const float u0 = cs[15] - mu0 * sV2;
                const float u1 = cs[18] - mu1 * sV2;
                const float u2 = cs[21] - mu2 * sV2;
                pen += i00 * u0 * u0 + i11 * u1 * u1 + i22 * u2 * u2
                     + 2.f * (i01 * u0 * u1 + i02 * u0 * u2 + i12 * u1 * u2);
            }

            const float wval = cs[12] - inv9 * pen;
            if (lane < WIN_PER_WARP) contrib += wval;
        }
    }

    // warp reduction
    #pragma unroll
    for (int off = 16; off > 0; off >>= 1)
        contrib += __shfl_xor_sync(0xffffffffu, contrib, off);

    __shared__ float wsum[WARPS_PER_BLOCK];
    __shared__ bool  is_last;
    if (lane == 0) wsum[warp_id] = contrib;
    __syncthreads();

    if (threadIdx.x == 0) {
        float s = 0.f;
        #pragma unroll
        for (int i = 0; i < WARPS_PER_BLOCK; i++) s += wsum[i];
        atomicAdd(&g_accum, (double)s);
        __threadfence();
        unsigned int prev = atomicAdd(&g_cnt, 1u);
        is_last = (prev == NBLOCKS - 1);
    }
    __syncthreads();

    if (is_last && threadIdx.x == 0) {
        __threadfence();
        out[0] = (float)g_accum;
        g_accum = 0.0;
        g_cnt   = 0;
    }
}

extern "C" void kernel_launch(void* const* d_in, const int* in_sizes, int n_in,
                              void* d_out, int out_size)
{
    const float* target = (const float*)d_in[0];
    const float* style  = (const float*)d_in[1];
    float* out = (float*)d_out;

    ml_fused_kernel<<<NBLOCKS, WARPS_PER_BLOCK * 32>>>(target, style, out);
}